// round 14
// baseline (speedup 1.0000x reference)
#include <cuda_runtime.h>
#include <cuda_fp16.h>
#include <cstdint>
#include <cstddef>

using half_t = __half;

#define SEQ  8192
#define DIN  1024
#define DOUT 1024
#define NTILES_N (SEQ / 128)     // 64 n-tiles per row in QK^T

// ---------------- device scratch (static: allowed) ----------------
__device__ half_t g_xh [SEQ * DIN];
__device__ half_t g_Wqh[DOUT * DIN];
__device__ half_t g_Wkh[DOUT * DIN];
__device__ half_t g_Wvh[DOUT * DIN];
__device__ half_t g_Qh [SEQ * DOUT];
__device__ half_t g_Kh [SEQ * DOUT];
__device__ half_t g_Vth[(size_t)DOUT * SEQ];    // V transposed [DOUT][SEQ]
__device__ half_t g_Ph [(size_t)SEQ * SEQ];     // unnormalized exp(scores), fp16
__device__ float  g_RSpart[SEQ * NTILES_N];     // per-(row, ntile) partial sums
__device__ float  g_InvRS[SEQ];                 // 1 / rowsum(exp)

// ---------------- helpers ----------------
__device__ __forceinline__ uint32_t smem_u32(const void* p) {
    uint32_t a;
    asm("{ .reg .u64 t; cvta.to.shared.u64 t, %1; cvt.u32.u64 %0, t; }" : "=r"(a) : "l"(p));
    return a;
}
__device__ __forceinline__ void cp16(uint32_t dst, const void* src) {
    asm volatile("cp.async.cg.shared.global [%0], [%1], 16;" :: "r"(dst), "l"(src));
}
#define CP_COMMIT() asm volatile("cp.async.commit_group;" ::: "memory")
#define CP_WAIT2()  asm volatile("cp.async.wait_group 2;" ::: "memory")

__device__ __forceinline__ void ldm4(uint32_t* r, uint32_t addr) {
    asm volatile("ldmatrix.sync.aligned.m8n8.x4.shared.b16 {%0,%1,%2,%3}, [%4];"
                 : "=r"(r[0]), "=r"(r[1]), "=r"(r[2]), "=r"(r[3]) : "r"(addr));
}
__device__ __forceinline__ void mma16816(float* d, const uint32_t* a, const uint32_t* b) {
    asm volatile(
        "mma.sync.aligned.m16n8k16.row.col.f32.f16.f16.f32 "
        "{%0,%1,%2,%3}, {%4,%5,%6,%7}, {%8,%9}, {%0,%1,%2,%3};"
        : "+f"(d[0]), "+f"(d[1]), "+f"(d[2]), "+f"(d[3])
        : "r"(a[0]), "r"(a[1]), "r"(a[2]), "r"(a[3]), "r"(b[0]), "r"(b[1]));
}

// ---------------- single merged conversion kernel (elementwise, order-free) ----------------
#define XN8 (SEQ * DIN / 8)
#define WN8 (DOUT * DIN / 8)
__global__ void convert_all_kernel(const float4* __restrict__ x,  const float4* __restrict__ wq,
                                   const float4* __restrict__ wk, const float4* __restrict__ wv,
                                   uint4* __restrict__ xh,  uint4* __restrict__ wqh,
                                   uint4* __restrict__ wkh, uint4* __restrict__ wvh) {
    int i = blockIdx.x * blockDim.x + threadIdx.x;
    const float4* src; uint4* dst; int j;
    if (i < XN8)                { src = x;  dst = xh;  j = i; }
    else if (i < XN8 + WN8)     { src = wq; dst = wqh; j = i - XN8; }
    else if (i < XN8 + 2 * WN8) { src = wk; dst = wkh; j = i - XN8 - WN8; }
    else if (i < XN8 + 3 * WN8) { src = wv; dst = wvh; j = i - XN8 - 2 * WN8; }
    else return;
    float4 a = src[2 * j];
    float4 b = src[2 * j + 1];
    __half2 h0 = __halves2half2(__float2half_rn(a.x), __float2half_rn(a.y));
    __half2 h1 = __halves2half2(__float2half_rn(a.z), __float2half_rn(a.w));
    __half2 h2 = __halves2half2(__float2half_rn(b.x), __float2half_rn(b.y));
    __half2 h3 = __halves2half2(__float2half_rn(b.z), __float2half_rn(b.w));
    uint4 o;
    o.x = *(uint32_t*)&h0;
    o.y = *(uint32_t*)&h1;
    o.z = *(uint32_t*)&h2;
    o.w = *(uint32_t*)&h3;
    dst[j] = o;
}

// ---------------- GEMM: C[MxN] = alpha * A[MxK] * B[NxK]^T (plain fp16) ----------------
#define OUT_PROJ  0
#define OUT_EXP   1
#define OUT_DIV   2

#define KT      32
#define STRIDE  40
#define TILE_H  (128 * STRIDE)
#define TILE_B  (TILE_H * 2)
#define STAGES  4
#define STAGE_B (2 * TILE_B)                  // 20480
#define GEMM_SMEM (STAGES * STAGE_B)          // 81920
#define RED_SMEM  (128 * 4 * 4)               // 2048: [128 rows][4 n-warps] floats
#define SMEM_TOTAL (GEMM_SMEM + RED_SMEM)     // 83968 -> 2 CTAs/SM (167936 < 228K)

template <int MODE>
__global__ __launch_bounds__(256, 2)
void gemm_nt_kernel(const half_t* __restrict__ Ah, const half_t* __restrict__ Bh,
                    const half_t* __restrict__ Bh2, const half_t* __restrict__ Bh3,
                    float* __restrict__ outF, half_t* __restrict__ outH,
                    half_t* __restrict__ outH2, half_t* __restrict__ outH3,
                    const float* __restrict__ invrs, float* __restrict__ rspart,
                    int K, int ldc, float alpha) {
    extern __shared__ half_t sm[];
    const uint32_t sbase = smem_u32(sm);
    const int tid  = threadIdx.x;
    const int lane = tid & 31;
    const int wid  = tid >> 5;
    const int m0 = blockIdx.y * 128;
    const int n0 = blockIdx.x * 128;
    const int wm = (wid & 1) * 64;
    const int wn = (wid >> 1) * 32;

    const int which = (MODE == OUT_PROJ) ? blockIdx.z : 0;
    const half_t* Bsel = Bh;
    if (MODE == OUT_PROJ) Bsel = (which == 0) ? Bh : (which == 1) ? Bh2 : Bh3;

    const int lrow = tid >> 1;
    const int lj   = (tid & 1) * 2;
    const half_t* srcA = Ah   + (size_t)(m0 + lrow) * K + lj * 8;
    const half_t* srcB = Bsel + (size_t)(n0 + lrow) * K + lj * 8;
    const uint32_t doff = (uint32_t)((lrow * STRIDE + lj * 8) * 2);

    auto load_stage = [&](int s, int kt) {
        uint32_t dstb = sbase + s * STAGE_B + doff;
        const int ko = kt * KT;
        cp16(dstb + 0,           srcA + ko);
        cp16(dstb + 16,          srcA + ko + 8);
        cp16(dstb + TILE_B + 0,  srcB + ko);
        cp16(dstb + TILE_B + 16, srcB + ko + 8);
    };

    float acc[4][4][4];
#pragma unroll
    for (int mt = 0; mt < 4; mt++)
#pragma unroll
        for (int nt = 0; nt < 4; nt++)
#pragma unroll
            for (int e = 0; e < 4; e++) acc[mt][nt][e] = 0.0f;

    const int arow    = wm + (lane & 15);
    const int acolsel = ((lane >> 4) & 1) * 8;
    const int brow    = wn + ((lane >> 4) & 1) * 8 + (lane & 7);
    const int bcolsel = ((lane >> 3) & 1) * 8;

    const int nkt = K / KT;
    load_stage(0, 0); CP_COMMIT();
    load_stage(1, 1); CP_COMMIT();
    load_stage(2, 2); CP_COMMIT();

#pragma unroll 1
    for (int kt = 0; kt < nkt; kt++) {
        CP_WAIT2();
        __syncthreads();
        if (kt + 3 < nkt) load_stage((kt + 3) & 3, kt + 3);
        CP_COMMIT();

        const uint32_t stb = sbase + (kt & 3) * STAGE_B;
#pragma unroll
        for (int kk = 0; kk < 2; kk++) {
            const int kc = kk * 16;
            uint32_t a_h[4][4], b_h[4][2];
#pragma unroll
            for (int mt = 0; mt < 4; mt++) {
                uint32_t off = (uint32_t)(((arow + mt * 16) * STRIDE + kc + acolsel) * 2);
                ldm4(a_h[mt], stb + off);
            }
#pragma unroll
            for (int pt = 0; pt < 2; pt++) {
                uint32_t off = (uint32_t)(((brow + pt * 16) * STRIDE + kc + bcolsel) * 2);
                uint32_t r[4];
                ldm4(r, stb + TILE_B + off);
                b_h[2 * pt][0] = r[0]; b_h[2 * pt][1] = r[1];
                b_h[2 * pt + 1][0] = r[2]; b_h[2 * pt + 1][1] = r[3];
            }
#pragma unroll
            for (int mt = 0; mt < 4; mt++)
#pragma unroll
                for (int nt = 0; nt < 4; nt++)
                    mma16816(acc[mt][nt], a_h[mt], b_h[nt]);
        }
    }

    // ---------------- epilogue ----------------
    const int rr = lane >> 2;
    const int cc = (lane & 3) * 2;
    float rsum[4][2];
    if (MODE == OUT_EXP) {
#pragma unroll
        for (int mt = 0; mt < 4; mt++) { rsum[mt][0] = 0.f; rsum[mt][1] = 0.f; }
    }
#pragma unroll
    for (int mt = 0; mt < 4; mt++) {
        int gm = m0 + wm + mt * 16 + rr;
        float inv0 = 0.f, inv1 = 0.f;
        if (MODE == OUT_DIV) { inv0 = invrs[gm]; inv1 = invrs[gm + 8]; }
#pragma unroll
        for (int nt = 0; nt < 4; nt++) {
            int gn = n0 + wn + nt * 8 + cc;
#pragma unroll
            for (int h = 0; h < 2; h++) {
                float v0 = acc[mt][nt][2 * h + 0] * alpha;
                float v1 = acc[mt][nt][2 * h + 1] * alpha;
                int m = gm + h * 8;
                if (MODE == OUT_PROJ) {
                    if (which == 0) {
                        *(__half2*)(outH + (size_t)m * DOUT + gn) =
                            __halves2half2(__float2half_rn(v0), __float2half_rn(v1));
                    } else if (which == 1) {
                        *(__half2*)(outH2 + (size_t)m * DOUT + gn) =
                            __halves2half2(__float2half_rn(v0), __float2half_rn(v1));
                    } else {
                        outH3[(size_t)gn * SEQ + m]       = __float2half_rn(v0);
                        outH3[(size_t)(gn + 1) * SEQ + m] = __float2half_rn(v1);
                    }
                } else if (MODE == OUT_EXP) {
                    half_t e0 = __float2half_rn(__expf(v0));
                    half_t e1 = __float2half_rn(__expf(v1));
                    *(__half2*)(outH + (size_t)m * ldc + gn) = __halves2half2(e0, e1);
                    rsum[mt][h] += __half2float(e0) + __half2float(e1);   // rounded values
                } else {  // OUT_DIV
                    float inv = (h == 0) ? inv0 : inv1;
                    float2 v; v.x = v0 * inv; v.y = v1 * inv;
                    *(float2*)(outF + (size_t)m * ldc + gn) = v;
                }
            }
        }
    }

    // ---------------- fused partial row-sum (EXP only, deterministic) ----------------
    if (MODE == OUT_EXP) {
        float* sm_part = (float*)((char*)sm + GEMM_SMEM);   // [128][4], separate region
        // quad butterfly: combine the 4 cc-lanes (fixed per-lane order; lane rr*4 used)
#pragma unroll
        for (int mt = 0; mt < 4; mt++)
#pragma unroll
            for (int h = 0; h < 2; h++) {
#pragma unroll
                for (int o = 1; o < 4; o <<= 1)
                    rsum[mt][h] += __shfl_xor_sync(0xFFFFFFFFu, rsum[mt][h], o);
            }
        __syncthreads();   // mainloop smem reads done before (harmless), order sm_part writes
        if ((lane & 3) == 0) {
            const int nw = wid >> 1;   // n-warp index 0..3
#pragma unroll
            for (int mt = 0; mt < 4; mt++)
#pragma unroll
                for (int h = 0; h < 2; h++) {
                    int row_local = wm + mt * 16 + rr + h * 8;
                    sm_part[row_local * 4 + nw] = rsum[mt][h];
                }
        }
        __syncthreads();
        if (tid < 128) {
            float s = sm_part[tid * 4 + 0] + sm_part[tid * 4 + 1]
                    + sm_part[tid * 4 + 2] + sm_part[tid * 4 + 3];
            rspart[(size_t)(m0 + tid) * NTILES_N + blockIdx.x] = s;
        }
    }
}

// ---------------- reduce partials -> 1/rowsum (deterministic index order) ----------------
__global__ __launch_bounds__(256)
void rowinv_reduce_kernel(const float* __restrict__ part, float* __restrict__ inv) {
    int row = blockIdx.x * blockDim.x + threadIdx.x;
    if (row < SEQ) {
        const float* p = part + (size_t)row * NTILES_N;
        float s = 0.0f;
#pragma unroll
        for (int j = 0; j < NTILES_N; j++) s += p[j];
        inv[row] = 1.0f / s;
    }
}

// ---------------- host ----------------
extern "C" void kernel_launch(void* const* d_in, const int* in_sizes, int n_in,
                              void* d_out, int out_size) {
    const float* x  = (const float*)d_in[0];
    const float* Wq = (const float*)d_in[1];
    const float* Wk = (const float*)d_in[2];
    const float* Wv = (const float*)d_in[3];
    float* out = (float*)d_out;

    half_t *xh, *wqh, *wkh, *wvh, *qh, *kh, *vth, *pph;
    float *invrs, *rsp;
    cudaGetSymbolAddress((void**)&xh,    g_xh);
    cudaGetSymbolAddress((void**)&wqh,   g_Wqh);
    cudaGetSymbolAddress((void**)&wkh,   g_Wkh);
    cudaGetSymbolAddress((void**)&wvh,   g_Wvh);
    cudaGetSymbolAddress((void**)&qh,    g_Qh);
    cudaGetSymbolAddress((void**)&kh,    g_Kh);
    cudaGetSymbolAddress((void**)&vth,   g_Vth);
    cudaGetSymbolAddress((void**)&pph,   g_Ph);
    cudaGetSymbolAddress((void**)&invrs, g_InvRS);
    cudaGetSymbolAddress((void**)&rsp,   g_RSpart);

    cudaFuncSetAttribute((const void*)gemm_nt_kernel<OUT_PROJ>,
                         cudaFuncAttributeMaxDynamicSharedMemorySize, SMEM_TOTAL);
    cudaFuncSetAttribute((const void*)gemm_nt_kernel<OUT_EXP>,
                         cudaFuncAttributeMaxDynamicSharedMemorySize, SMEM_TOTAL);
    cudaFuncSetAttribute((const void*)gemm_nt_kernel<OUT_DIV>,
                         cudaFuncAttributeMaxDynamicSharedMemorySize, SMEM_TOTAL);

    // 1) convert all fp32 inputs to fp16 in ONE launch
    {
        int total8 = XN8 + 3 * WN8;
        convert_all_kernel<<<(total8 + 255) / 256, 256>>>(
            (const float4*)x, (const float4*)Wq, (const float4*)Wk, (const float4*)Wv,
            (uint4*)xh, (uint4*)wqh, (uint4*)wkh, (uint4*)wvh);
    }

    // 2) ALL projections in ONE launch: z=0 Q, z=1 K, z=2 V^T
    dim3 gproj(DOUT / 128, SEQ / 128, 3);
    gemm_nt_kernel<OUT_PROJ><<<gproj, 256, SMEM_TOTAL>>>(
        xh, wqh, wkh, wvh, nullptr, qh, kh, vth, nullptr, nullptr, DIN, DOUT, 1.0f);

    // 3) scores + exp + fused partial row-sums: P~ = exp(Q K^T / 32)
    dim3 gsc(SEQ / 128, SEQ / 128);
    gemm_nt_kernel<OUT_EXP><<<gsc, 256, SMEM_TOTAL>>>(
        qh, kh, nullptr, nullptr, nullptr, pph, nullptr, nullptr, nullptr, rsp, DIN, SEQ, 0.03125f);

    // 4) reduce 64 partials per row -> 1/rowsum (2 MB, ~3 us)
    rowinv_reduce_kernel<<<SEQ / 256, 256>>>(rsp, invrs);

    // 5) O = (P~ V) * invrs[m]
    dim3 gout(DOUT / 128, SEQ / 128);
    gemm_nt_kernel<OUT_DIV><<<gout, 256, SMEM_TOTAL>>>(
        pph, vth, nullptr, nullptr, out, nullptr, nullptr, nullptr, invrs, nullptr, SEQ, DOUT, 1.0f);
}

// round 15
// speedup vs baseline: 1.0198x; 1.0198x over previous
#include <cuda_runtime.h>
#include <cuda_fp16.h>
#include <cstdint>
#include <cstddef>

using half_t = __half;

#define SEQ  8192
#define DIN  1024
#define DOUT 1024
#define NTILES_N (SEQ / 128)     // 64 n-tiles per row in QK^T

// ---------------- device scratch (static: allowed) ----------------
__device__ half_t g_xh [SEQ * DIN];
__device__ half_t g_Wqh[DOUT * DIN];
__device__ half_t g_Wkh[DOUT * DIN];
__device__ half_t g_Wvh[DOUT * DIN];
__device__ half_t g_Qh [SEQ * DOUT];
__device__ half_t g_Kh [SEQ * DOUT];
__device__ half_t g_Vth[(size_t)DOUT * SEQ];    // V transposed [DOUT][SEQ]
__device__ half_t g_Ph [(size_t)SEQ * SEQ];     // unnormalized exp(scores), fp16
__device__ float  g_RSpart[NTILES_N * SEQ];     // partial sums, [ntile][row] (coalesced)

// ---------------- helpers ----------------
__device__ __forceinline__ uint32_t smem_u32(const void* p) {
    uint32_t a;
    asm("{ .reg .u64 t; cvta.to.shared.u64 t, %1; cvt.u32.u64 %0, t; }" : "=r"(a) : "l"(p));
    return a;
}
__device__ __forceinline__ void cp16(uint32_t dst, const void* src) {
    asm volatile("cp.async.cg.shared.global [%0], [%1], 16;" :: "r"(dst), "l"(src));
}
#define CP_COMMIT() asm volatile("cp.async.commit_group;" ::: "memory")
#define CP_WAIT2()  asm volatile("cp.async.wait_group 2;" ::: "memory")

__device__ __forceinline__ void ldm4(uint32_t* r, uint32_t addr) {
    asm volatile("ldmatrix.sync.aligned.m8n8.x4.shared.b16 {%0,%1,%2,%3}, [%4];"
                 : "=r"(r[0]), "=r"(r[1]), "=r"(r[2]), "=r"(r[3]) : "r"(addr));
}
__device__ __forceinline__ void mma16816(float* d, const uint32_t* a, const uint32_t* b) {
    asm volatile(
        "mma.sync.aligned.m16n8k16.row.col.f32.f16.f16.f32 "
        "{%0,%1,%2,%3}, {%4,%5,%6,%7}, {%8,%9}, {%0,%1,%2,%3};"
        : "+f"(d[0]), "+f"(d[1]), "+f"(d[2]), "+f"(d[3])
        : "r"(a[0]), "r"(a[1]), "r"(a[2]), "r"(a[3]), "r"(b[0]), "r"(b[1]));
}

// ---------------- single merged conversion kernel (elementwise, order-free) ----------------
#define XN8 (SEQ * DIN / 8)
#define WN8 (DOUT * DIN / 8)
__global__ void convert_all_kernel(const float4* __restrict__ x,  const float4* __restrict__ wq,
                                   const float4* __restrict__ wk, const float4* __restrict__ wv,
                                   uint4* __restrict__ xh,  uint4* __restrict__ wqh,
                                   uint4* __restrict__ wkh, uint4* __restrict__ wvh) {
    int i = blockIdx.x * blockDim.x + threadIdx.x;
    const float4* src; uint4* dst; int j;
    if (i < XN8)                { src = x;  dst = xh;  j = i; }
    else if (i < XN8 + WN8)     { src = wq; dst = wqh; j = i - XN8; }
    else if (i < XN8 + 2 * WN8) { src = wk; dst = wkh; j = i - XN8 - WN8; }
    else if (i < XN8 + 3 * WN8) { src = wv; dst = wvh; j = i - XN8 - 2 * WN8; }
    else return;
    float4 a = src[2 * j];
    float4 b = src[2 * j + 1];
    __half2 h0 = __halves2half2(__float2half_rn(a.x), __float2half_rn(a.y));
    __half2 h1 = __halves2half2(__float2half_rn(a.z), __float2half_rn(a.w));
    __half2 h2 = __halves2half2(__float2half_rn(b.x), __float2half_rn(b.y));
    __half2 h3 = __halves2half2(__float2half_rn(b.z), __float2half_rn(b.w));
    uint4 o;
    o.x = *(uint32_t*)&h0;
    o.y = *(uint32_t*)&h1;
    o.z = *(uint32_t*)&h2;
    o.w = *(uint32_t*)&h3;
    dst[j] = o;
}

// ---------------- GEMM: C[MxN] = alpha * A[MxK] * B[NxK]^T (plain fp16) ----------------
#define OUT_PROJ  0
#define OUT_EXP   1
#define OUT_DIV   2

#define KT      32
#define STRIDE  40
#define TILE_H  (128 * STRIDE)
#define TILE_B  (TILE_H * 2)
#define STAGES  4
#define STAGE_B (2 * TILE_B)                  // 20480
#define GEMM_SMEM (STAGES * STAGE_B)          // 81920
#define RED_SMEM  2048                        // partial-sum / inv staging region
#define SMEM_TOTAL (GEMM_SMEM + RED_SMEM)     // 83968 -> 2 CTAs/SM (167936 < 228K)

template <int MODE>
__global__ __launch_bounds__(256, 2)
void gemm_nt_kernel(const half_t* __restrict__ Ah, const half_t* __restrict__ Bh,
                    const half_t* __restrict__ Bh2, const half_t* __restrict__ Bh3,
                    float* __restrict__ outF, half_t* __restrict__ outH,
                    half_t* __restrict__ outH2, half_t* __restrict__ outH3,
                    float* __restrict__ rspart,
                    int K, int ldc, float alpha) {
    extern __shared__ half_t sm[];
    const uint32_t sbase = smem_u32(sm);
    const int tid  = threadIdx.x;
    const int lane = tid & 31;
    const int wid  = tid >> 5;
    const int m0 = blockIdx.y * 128;
    const int n0 = blockIdx.x * 128;
    const int wm = (wid & 1) * 64;
    const int wn = (wid >> 1) * 32;

    const int which = (MODE == OUT_PROJ) ? blockIdx.z : 0;
    const half_t* Bsel = Bh;
    if (MODE == OUT_PROJ) Bsel = (which == 0) ? Bh : (which == 1) ? Bh2 : Bh3;

    const int lrow = tid >> 1;
    const int lj   = (tid & 1) * 2;
    const half_t* srcA = Ah   + (size_t)(m0 + lrow) * K + lj * 8;
    const half_t* srcB = Bsel + (size_t)(n0 + lrow) * K + lj * 8;
    const uint32_t doff = (uint32_t)((lrow * STRIDE + lj * 8) * 2);

    auto load_stage = [&](int s, int kt) {
        uint32_t dstb = sbase + s * STAGE_B + doff;
        const int ko = kt * KT;
        cp16(dstb + 0,           srcA + ko);
        cp16(dstb + 16,          srcA + ko + 8);
        cp16(dstb + TILE_B + 0,  srcB + ko);
        cp16(dstb + TILE_B + 16, srcB + ko + 8);
    };

    float acc[4][4][4];
#pragma unroll
    for (int mt = 0; mt < 4; mt++)
#pragma unroll
        for (int nt = 0; nt < 4; nt++)
#pragma unroll
            for (int e = 0; e < 4; e++) acc[mt][nt][e] = 0.0f;

    const int arow    = wm + (lane & 15);
    const int acolsel = ((lane >> 4) & 1) * 8;
    const int brow    = wn + ((lane >> 4) & 1) * 8 + (lane & 7);
    const int bcolsel = ((lane >> 3) & 1) * 8;

    const int nkt = K / KT;
    load_stage(0, 0); CP_COMMIT();
    load_stage(1, 1); CP_COMMIT();
    load_stage(2, 2); CP_COMMIT();

#pragma unroll 1
    for (int kt = 0; kt < nkt; kt++) {
        CP_WAIT2();
        __syncthreads();
        if (kt + 3 < nkt) load_stage((kt + 3) & 3, kt + 3);
        CP_COMMIT();

        const uint32_t stb = sbase + (kt & 3) * STAGE_B;
#pragma unroll
        for (int kk = 0; kk < 2; kk++) {
            const int kc = kk * 16;
            uint32_t a_h[4][4], b_h[4][2];
#pragma unroll
            for (int mt = 0; mt < 4; mt++) {
                uint32_t off = (uint32_t)(((arow + mt * 16) * STRIDE + kc + acolsel) * 2);
                ldm4(a_h[mt], stb + off);
            }
#pragma unroll
            for (int pt = 0; pt < 2; pt++) {
                uint32_t off = (uint32_t)(((brow + pt * 16) * STRIDE + kc + bcolsel) * 2);
                uint32_t r[4];
                ldm4(r, stb + TILE_B + off);
                b_h[2 * pt][0] = r[0]; b_h[2 * pt][1] = r[1];
                b_h[2 * pt + 1][0] = r[2]; b_h[2 * pt + 1][1] = r[3];
            }
#pragma unroll
            for (int mt = 0; mt < 4; mt++)
#pragma unroll
                for (int nt = 0; nt < 4; nt++)
                    mma16816(acc[mt][nt], a_h[mt], b_h[nt]);
        }
    }

    // ---------------- PV: compute 1/rowsum inline (same j-order as old reduce) ----------------
    float* sm_red = (float*)((char*)sm + GEMM_SMEM);   // RED_SMEM region
    if (MODE == OUT_DIV) {
        __syncthreads();          // mainloop smem reads complete (region separate, but order anyway)
        if (tid < 128) {
            const float* p = rspart + (m0 + tid);
            float s = 0.0f;
#pragma unroll
            for (int j = 0; j < NTILES_N; j++) s += p[(size_t)j * SEQ];
            sm_red[tid] = 1.0f / s;
        }
        __syncthreads();
    }

    // ---------------- epilogue ----------------
    const int rr = lane >> 2;
    const int cc = (lane & 3) * 2;
    float rsum[4][2];
    if (MODE == OUT_EXP) {
#pragma unroll
        for (int mt = 0; mt < 4; mt++) { rsum[mt][0] = 0.f; rsum[mt][1] = 0.f; }
    }
#pragma unroll
    for (int mt = 0; mt < 4; mt++) {
        int gm = m0 + wm + mt * 16 + rr;
        float inv0 = 0.f, inv1 = 0.f;
        if (MODE == OUT_DIV) {
            inv0 = sm_red[wm + mt * 16 + rr];
            inv1 = sm_red[wm + mt * 16 + rr + 8];
        }
#pragma unroll
        for (int nt = 0; nt < 4; nt++) {
            int gn = n0 + wn + nt * 8 + cc;
#pragma unroll
            for (int h = 0; h < 2; h++) {
                float v0 = acc[mt][nt][2 * h + 0] * alpha;
                float v1 = acc[mt][nt][2 * h + 1] * alpha;
                int m = gm + h * 8;
                if (MODE == OUT_PROJ) {
                    if (which == 0) {
                        *(__half2*)(outH + (size_t)m * DOUT + gn) =
                            __halves2half2(__float2half_rn(v0), __float2half_rn(v1));
                    } else if (which == 1) {
                        *(__half2*)(outH2 + (size_t)m * DOUT + gn) =
                            __halves2half2(__float2half_rn(v0), __float2half_rn(v1));
                    } else {
                        outH3[(size_t)gn * SEQ + m]       = __float2half_rn(v0);
                        outH3[(size_t)(gn + 1) * SEQ + m] = __float2half_rn(v1);
                    }
                } else if (MODE == OUT_EXP) {
                    half_t e0 = __float2half_rn(__expf(v0));
                    half_t e1 = __float2half_rn(__expf(v1));
                    *(__half2*)(outH + (size_t)m * ldc + gn) = __halves2half2(e0, e1);
                    rsum[mt][h] += __half2float(e0) + __half2float(e1);   // rounded values
                } else {  // OUT_DIV
                    float inv = (h == 0) ? inv0 : inv1;
                    float2 v; v.x = v0 * inv; v.y = v1 * inv;
                    *(float2*)(outF + (size_t)m * ldc + gn) = v;
                }
            }
        }
    }

    // ---------------- fused partial row-sum (EXP only, deterministic) ----------------
    if (MODE == OUT_EXP) {
#pragma unroll
        for (int mt = 0; mt < 4; mt++)
#pragma unroll
            for (int h = 0; h < 2; h++) {
#pragma unroll
                for (int o = 1; o < 4; o <<= 1)
                    rsum[mt][h] += __shfl_xor_sync(0xFFFFFFFFu, rsum[mt][h], o);
            }
        __syncthreads();
        if ((lane & 3) == 0) {
            const int nw = wid >> 1;   // n-warp index 0..3
#pragma unroll
            for (int mt = 0; mt < 4; mt++)
#pragma unroll
                for (int h = 0; h < 2; h++) {
                    int row_local = wm + mt * 16 + rr + h * 8;
                    sm_red[row_local * 4 + nw] = rsum[mt][h];
                }
        }
        __syncthreads();
        if (tid < 128) {
            float s = sm_red[tid * 4 + 0] + sm_red[tid * 4 + 1]
                    + sm_red[tid * 4 + 2] + sm_red[tid * 4 + 3];
            // transposed layout [ntile][row]: coalesced write AND coalesced PV read
            rspart[(size_t)blockIdx.x * SEQ + m0 + tid] = s;
        }
    }
}

// ---------------- host ----------------
extern "C" void kernel_launch(void* const* d_in, const int* in_sizes, int n_in,
                              void* d_out, int out_size) {
    const float* x  = (const float*)d_in[0];
    const float* Wq = (const float*)d_in[1];
    const float* Wk = (const float*)d_in[2];
    const float* Wv = (const float*)d_in[3];
    float* out = (float*)d_out;

    half_t *xh, *wqh, *wkh, *wvh, *qh, *kh, *vth, *pph;
    float *rsp;
    cudaGetSymbolAddress((void**)&xh,  g_xh);
    cudaGetSymbolAddress((void**)&wqh, g_Wqh);
    cudaGetSymbolAddress((void**)&wkh, g_Wkh);
    cudaGetSymbolAddress((void**)&wvh, g_Wvh);
    cudaGetSymbolAddress((void**)&qh,  g_Qh);
    cudaGetSymbolAddress((void**)&kh,  g_Kh);
    cudaGetSymbolAddress((void**)&vth, g_Vth);
    cudaGetSymbolAddress((void**)&pph, g_Ph);
    cudaGetSymbolAddress((void**)&rsp, g_RSpart);

    cudaFuncSetAttribute((const void*)gemm_nt_kernel<OUT_PROJ>,
                         cudaFuncAttributeMaxDynamicSharedMemorySize, SMEM_TOTAL);
    cudaFuncSetAttribute((const void*)gemm_nt_kernel<OUT_EXP>,
                         cudaFuncAttributeMaxDynamicSharedMemorySize, SMEM_TOTAL);
    cudaFuncSetAttribute((const void*)gemm_nt_kernel<OUT_DIV>,
                         cudaFuncAttributeMaxDynamicSharedMemorySize, SMEM_TOTAL);

    // 1) convert all fp32 inputs to fp16 in ONE launch
    {
        int total8 = XN8 + 3 * WN8;
        convert_all_kernel<<<(total8 + 255) / 256, 256>>>(
            (const float4*)x, (const float4*)Wq, (const float4*)Wk, (const float4*)Wv,
            (uint4*)xh, (uint4*)wqh, (uint4*)wkh, (uint4*)wvh);
    }

    // 2) ALL projections in ONE launch: z=0 Q, z=1 K, z=2 V^T
    dim3 gproj(DOUT / 128, SEQ / 128, 3);
    gemm_nt_kernel<OUT_PROJ><<<gproj, 256, SMEM_TOTAL>>>(
        xh, wqh, wkh, wvh, nullptr, qh, kh, vth, nullptr, DIN, DOUT, 1.0f);

    // 3) scores + exp + fused partial row-sums: P~ = exp(Q K^T / 32)
    dim3 gsc(SEQ / 128, SEQ / 128);
    gemm_nt_kernel<OUT_EXP><<<gsc, 256, SMEM_TOTAL>>>(
        qh, kh, nullptr, nullptr, nullptr, pph, nullptr, nullptr, rsp, DIN, SEQ, 0.03125f);

    // 4) O = (P~ V) * (1/rowsum) — rowsum folded into the PV epilogue (no reduce kernel)
    dim3 gout(DOUT / 128, SEQ / 128);
    gemm_nt_kernel<OUT_DIV><<<gout, 256, SMEM_TOTAL>>>(
        pph, vth, nullptr, nullptr, out, nullptr, nullptr, nullptr, rsp, SEQ, DOUT, 1.0f);
}